// round 11
// baseline (speedup 1.0000x reference)
#include <cuda_runtime.h>

#define DV 160
#define HV 192
#define WV 160
#define VOL (DV * HV * WV)     // 4,915,200
#define SLICE (HV * WV)        // 30,720

// ---- Tile geometry: 32x16x4 voxels, 2400 blocks (8.1 waves @ 2 blocks/SM) ----
#define TX 32
#define TY 16
#define TZ 4
#define HXL 8                   // x halo low (keeps rows float4-aligned)
#define HYL 5
#define HZL 6
#define EX 48                   // x: [tx0-8, tx0+40)
#define EY 27                   // y: [ty0-5, ty0+22)
#define EZ 17                   // z: [tz0-6, tz0+11)
#define EXY (EX * EY)           // 1296
#define SMEM_ELEMS (EX * EY * EZ)    // 22032
#define SMEM_BYTES (SMEM_ELEMS * 4)  // 88,128 -> 2 blocks/SM
#define NTHREADS 512

// Generic zero-padding trilinear for the 3-channel flow1 volume (rare path:
// stage-1 coords are effectively un-normalized twice -> >99.99% fully OOB).
__device__ __noinline__ void tri3_slow(const float* __restrict__ vol,
                                       float ix, float iy, float iz,
                                       float* __restrict__ o) {
    float x0f = floorf(ix), y0f = floorf(iy), z0f = floorf(iz);
    float tx = ix - x0f, ty = iy - y0f, tz = iz - z0f;
    int x0 = (int)x0f, y0 = (int)y0f, z0 = (int)z0f;
    float wx[2] = {1.f - tx, tx};
    float wy[2] = {1.f - ty, ty};
    float wz[2] = {1.f - tz, tz};
#pragma unroll
    for (int dz = 0; dz < 2; dz++) {
        int zc = z0 + dz;
        if (zc < 0 || zc >= DV) continue;
#pragma unroll
        for (int dy = 0; dy < 2; dy++) {
            int yc = y0 + dy;
            if (yc < 0 || yc >= HV) continue;
            int base = (zc * HV + yc) * WV;
            float wzy = wz[dz] * wy[dy];
#pragma unroll
            for (int dx = 0; dx < 2; dx++) {
                int xc = x0 + dx;
                if (xc < 0 || xc >= WV) continue;
                float wgt = wzy * wx[dx];
                int off = base + xc;
                o[0] = fmaf(__ldg(vol + off),           wgt, o[0]);
                o[1] = fmaf(__ldg(vol + VOL + off),     wgt, o[1]);
                o[2] = fmaf(__ldg(vol + 2 * VOL + off), wgt, o[2]);
            }
        }
    }
}

// Fallback: global-memory src sample (zeros padding) for voxels whose stencil
// escapes the smem halo (~0.3% of voxels).
__device__ __noinline__ float tri1_global(const float* __restrict__ vol,
                                          int x0, int y0, int z0,
                                          float tx, float ty, float tz) {
    if (x0 <= -2 || x0 >= WV || y0 <= -2 || y0 >= HV || z0 <= -2 || z0 >= DV)
        return 0.f;
    float wx[2] = {1.f - tx, tx};
    float wy[2] = {1.f - ty, ty};
    float wz[2] = {1.f - tz, tz};
    float acc = 0.f;
#pragma unroll
    for (int dz = 0; dz < 2; dz++) {
        int zc = z0 + dz;
        if (zc < 0 || zc >= DV) continue;
#pragma unroll
        for (int dy = 0; dy < 2; dy++) {
            int yc = y0 + dy;
            if (yc < 0 || yc >= HV) continue;
            int base = (zc * HV + yc) * WV;
            float wzy = wz[dz] * wy[dy];
#pragma unroll
            for (int dx = 0; dx < 2; dx++) {
                int xc = x0 + dx;
                if (xc < 0 || xc >= WV) continue;
                acc = fmaf(__ldg(vol + base + xc), wzy * wx[dx], acc);
            }
        }
    }
    return acc;
}

__global__ void __launch_bounds__(NTHREADS, 2)
spatial_transformer_tiled(const float* __restrict__ src,
                          const float* __restrict__ flow1,
                          const float* __restrict__ flow2,
                          const float* __restrict__ rf_ptr,
                          float* __restrict__ out) {
    extern __shared__ float tile[];

    const int tx0 = blockIdx.x * TX;
    const int ty0 = blockIdx.y * TY;
    const int tz0 = blockIdx.z * TZ;
    const int sxlo = tx0 - HXL;
    const int sylo = ty0 - HYL;
    const int szlo = tz0 - HZL;

    // ---- Stage src tile (+halo) into smem with float4 rows.
    // Volume-OOB cells -> 0 (zeros padding becomes free in the fast path).
#pragma unroll 2
    for (int e4 = threadIdx.x; e4 < SMEM_ELEMS / 4; e4 += NTHREADS) {
        int ex4 = e4 % (EX / 4);          // 0..11
        int row = e4 / (EX / 4);
        int ey  = row % EY;
        int ez  = row / EY;
        int gx = sxlo + ex4 * 4;
        int gy = sylo + ey;
        int gz = szlo + ez;
        float4 v = make_float4(0.f, 0.f, 0.f, 0.f);
        if ((unsigned)gy < HV && (unsigned)gz < DV) {
            const float* p = src + (gz * HV + gy) * WV + gx;
            if (gx >= 0 && gx + 3 < WV) {
                v = __ldg((const float4*)p);          // aligned: gx % 4 == 0
            } else {
                if ((unsigned)(gx + 0) < WV) v.x = __ldg(p + 0);
                if ((unsigned)(gx + 1) < WV) v.y = __ldg(p + 1);
                if ((unsigned)(gx + 2) < WV) v.z = __ldg(p + 2);
                if ((unsigned)(gx + 3) < WV) v.w = __ldg(p + 3);
            }
        }
        ((float4*)tile)[e4] = v;
    }

    const int lx = threadIdx.x & 31;      // warp lanes span x (coalesced I/O)
    const int ly = threadIdx.x >> 5;      // 0..15
    const int w = tx0 + lx;
    const int h = ty0 + ly;
    const float wf = (float)w, hf = (float)h;

    const float rf = __ldg(rf_ptr);
    const float CD = (float)DV / (float)(DV - 1);
    const float CH = (float)HV / (float)(HV - 1);
    const float CW = (float)WV / (float)(WV - 1);

    const int idx0 = (tz0 * HV + h) * WV + w;

    // Software pipeline: prefetch slice 0's flow2 before the barrier so the
    // DRAM latency overlaps the staging store + sync.
    float nf2z = __ldg(flow2 + idx0);
    float nf2y = __ldg(flow2 + VOL + idx0);
    float nf2x = __ldg(flow2 + 2 * VOL + idx0);

    __syncthreads();

#pragma unroll
    for (int i = 0; i < TZ; i++) {
        const int d = tz0 + i;
        const float df = (float)d;
        const int idx = idx0 + i * SLICE;

        float f2z = nf2z, f2y = nf2y, f2x = nf2x;
        if (i < TZ - 1) {                  // prefetch next slice's flow2
            nf2z = __ldg(flow2 + idx + SLICE);
            nf2y = __ldg(flow2 + VOL + idx + SLICE);
            nf2x = __ldg(flow2 + 2 * VOL + idx + SLICE);
        }

        // ---- Stage 1: flow1 warped by grid+flow2*rf (coords treated as
        // normalized -> almost always fully OOB -> zero).
        float gz1 = df + f2z * rf;
        float gy1 = hf + f2y * rf;
        float gx1 = wf + f2x * rf;
        float iz1 = fmaf(gz1, 80.f, 79.5f);   // ((g+1)*160-1)/2
        float iy1 = fmaf(gy1, 96.f, 95.5f);   // ((g+1)*192-1)/2
        float ix1 = fmaf(gx1, 80.f, 79.5f);

        float fw[3] = {0.f, 0.f, 0.f};
        if (ix1 >= -1.f && ix1 < (float)WV &&
            iy1 >= -1.f && iy1 < (float)HV &&
            iz1 >= -1.f && iz1 < (float)DV) {
            tri3_slow(flow1, ix1, iy1, iz1, fw);
        }
        float of0 = fw[0] + f2z;
        float of1 = fw[1] + f2y;
        float of2 = fw[2] + f2x;

        // ---- Stage 2: resample src at grid + out_flow*rf (renormalized).
        float nl0 = df + of0 * rf;
        float nl1 = hf + of1 * rf;
        float nl2 = wf + of2 * rf;
        float iz2 = fmaf(nl0, CD, -0.5f);
        float iy2 = fmaf(nl1, CH, -0.5f);
        float ix2 = fmaf(nl2, CW, -0.5f);

        float x0f = floorf(ix2), y0f = floorf(iy2), z0f = floorf(iz2);
        float tx = ix2 - x0f, ty = iy2 - y0f, tz = iz2 - z0f;
        int x0 = (int)x0f, y0 = (int)y0f, z0 = (int)z0f;
        int sx = x0 - sxlo, sy = y0 - sylo, sz = z0 - szlo;

        float img;
        if ((unsigned)sx <= (EX - 2) &&
            (unsigned)sy <= (EY - 2) &&
            (unsigned)sz <= (EZ - 2)) {
            const float* p = tile + (sz * EY + sy) * EX + sx;
            const float* q = p + EXY;
            float v000 = p[0],  v001 = p[1];
            float v010 = p[EX], v011 = p[EX + 1];
            float v100 = q[0],  v101 = q[1];
            float v110 = q[EX], v111 = q[EX + 1];
            float c00 = fmaf(v001 - v000, tx, v000);
            float c01 = fmaf(v011 - v010, tx, v010);
            float c10 = fmaf(v101 - v100, tx, v100);
            float c11 = fmaf(v111 - v110, tx, v110);
            float c0  = fmaf(c01 - c00, ty, c00);
            float c1  = fmaf(c11 - c10, ty, c10);
            img = fmaf(c1 - c0, tz, c0);
        } else {
            img = tri1_global(src, x0, y0, z0, tx, ty, tz);
        }

        // ---- Outputs: deform_2_img [V], then out_flow [3V].
        out[idx]           = img;
        out[VOL + idx]     = of0;
        out[2 * VOL + idx] = of1;
        out[3 * VOL + idx] = of2;
    }
}

extern "C" void kernel_launch(void* const* d_in, const int* in_sizes, int n_in,
                              void* d_out, int out_size) {
    const float* src   = (const float*)d_in[0];
    const float* flow1 = (const float*)d_in[1];
    const float* flow2 = (const float*)d_in[2];
    // d_in[3] = meshgrid (recomputed in-kernel)
    const float* rf    = (const float*)d_in[4];
    float* out = (float*)d_out;

    // Deterministic, capture-safe: opt in to >48KB dynamic smem.
    cudaFuncSetAttribute(spatial_transformer_tiled,
                         cudaFuncAttributeMaxDynamicSharedMemorySize,
                         SMEM_BYTES);

    dim3 grid(WV / TX, HV / TY, DV / TZ);   // 5 x 12 x 40 = 2400 blocks
    spatial_transformer_tiled<<<grid, NTHREADS, SMEM_BYTES>>>(src, flow1, flow2,
                                                              rf, out);
}

// round 15
// speedup vs baseline: 1.1301x; 1.1301x over previous
#include <cuda_runtime.h>

#define DV 160
#define HV 192
#define WV 160
#define VOL (DV * HV * WV)     // 4,915,200
#define SLICE (HV * WV)        // 30,720

// ---- Tile: 32x32x8 voxels, one 1024-thread block, 600 blocks ----
#define TX 32
#define TY 32
#define TZ 8
#define HXL 8                   // x halo low (mult of 4: float4-aligned rows)
#define HYL 8
#define HZL 7
#define EX 48                   // x: [tx0-8, tx0+40)   margins 8 / 7
#define EY 49                   // y: [ty0-8, ty0+41)   margins 8 / 8
#define EZ 22                   // z: [tz0-7, tz0+15)   margins 7 / 6
#define EXY (EX * EY)           // 2352
#define SMEM_ELEMS (EX * EY * EZ)    // 51744
#define SMEM_BYTES (SMEM_ELEMS * 4)  // 206,976 B -> 1 block/SM, 32 warps
#define NTHREADS 1024

// Zero-padding trilinear for the 3-channel flow1 volume. Rare path (stage-1
// coords are effectively un-normalized twice -> >99.99% of voxels fully OOB).
// Takes the pre-unnormalization coords and derives exact sample coords here.
__device__ __noinline__ void tri3_slow(const float* __restrict__ vol,
                                       float gx1, float gy1, float gz1,
                                       float* __restrict__ o) {
    float ix = fmaf(gx1, 80.f, 79.5f);   // ((g+1)*160-1)/2
    float iy = fmaf(gy1, 96.f, 95.5f);   // ((g+1)*192-1)/2
    float iz = fmaf(gz1, 80.f, 79.5f);
    float x0f = floorf(ix), y0f = floorf(iy), z0f = floorf(iz);
    float tx = ix - x0f, ty = iy - y0f, tz = iz - z0f;
    int x0 = (int)x0f, y0 = (int)y0f, z0 = (int)z0f;
    float wx[2] = {1.f - tx, tx};
    float wy[2] = {1.f - ty, ty};
    float wz[2] = {1.f - tz, tz};
#pragma unroll
    for (int dz = 0; dz < 2; dz++) {
        int zc = z0 + dz;
        if (zc < 0 || zc >= DV) continue;
#pragma unroll
        for (int dy = 0; dy < 2; dy++) {
            int yc = y0 + dy;
            if (yc < 0 || yc >= HV) continue;
            int base = (zc * HV + yc) * WV;
            float wzy = wz[dz] * wy[dy];
#pragma unroll
            for (int dx = 0; dx < 2; dx++) {
                int xc = x0 + dx;
                if (xc < 0 || xc >= WV) continue;
                float wgt = wzy * wx[dx];
                int off = base + xc;
                o[0] = fmaf(__ldg(vol + off),           wgt, o[0]);
                o[1] = fmaf(__ldg(vol + VOL + off),     wgt, o[1]);
                o[2] = fmaf(__ldg(vol + 2 * VOL + off), wgt, o[2]);
            }
        }
    }
}

// Fallback: global-memory src sample (zeros padding) for voxels whose stencil
// escapes the smem halo (~0.1% of voxels with the wide halos).
__device__ __noinline__ float tri1_global(const float* __restrict__ vol,
                                          int x0, int y0, int z0,
                                          float tx, float ty, float tz) {
    if (x0 <= -2 || x0 >= WV || y0 <= -2 || y0 >= HV || z0 <= -2 || z0 >= DV)
        return 0.f;
    float wx[2] = {1.f - tx, tx};
    float wy[2] = {1.f - ty, ty};
    float wz[2] = {1.f - tz, tz};
    float acc = 0.f;
#pragma unroll
    for (int dz = 0; dz < 2; dz++) {
        int zc = z0 + dz;
        if (zc < 0 || zc >= DV) continue;
#pragma unroll
        for (int dy = 0; dy < 2; dy++) {
            int yc = y0 + dy;
            if (yc < 0 || yc >= HV) continue;
            int base = (zc * HV + yc) * WV;
            float wzy = wz[dz] * wy[dy];
#pragma unroll
            for (int dx = 0; dx < 2; dx++) {
                int xc = x0 + dx;
                if (xc < 0 || xc >= WV) continue;
                acc = fmaf(__ldg(vol + base + xc), wzy * wx[dx], acc);
            }
        }
    }
    return acc;
}

__global__ void __launch_bounds__(NTHREADS, 1)
spatial_transformer_tiled(const float* __restrict__ src,
                          const float* __restrict__ flow1,
                          const float* __restrict__ flow2,
                          const float* __restrict__ rf_ptr,
                          float* __restrict__ out) {
    extern __shared__ float tile[];

    const int tx0 = blockIdx.x * TX;
    const int ty0 = blockIdx.y * TY;
    const int tz0 = blockIdx.z * TZ;
    const int sxlo = tx0 - HXL;
    const int sylo = ty0 - HYL;
    const int szlo = tz0 - HZL;

    // ---- Stage src tile (+halo) into smem with float4 rows.
    // Volume-OOB cells -> 0 (zeros padding becomes free in the fast path).
#pragma unroll 2
    for (int e4 = threadIdx.x; e4 < SMEM_ELEMS / 4; e4 += NTHREADS) {
        int ex4 = e4 % (EX / 4);          // 0..11
        int row = e4 / (EX / 4);
        int ey  = row % EY;
        int ez  = row / EY;
        int gx = sxlo + ex4 * 4;
        int gy = sylo + ey;
        int gz = szlo + ez;
        float4 v = make_float4(0.f, 0.f, 0.f, 0.f);
        if ((unsigned)gy < HV && (unsigned)gz < DV) {
            const float* p = src + (gz * HV + gy) * WV + gx;
            if (gx >= 0 && gx + 3 < WV) {
                v = __ldg((const float4*)p);          // aligned: gx % 4 == 0
            } else {
                if ((unsigned)(gx + 0) < WV) v.x = __ldg(p + 0);
                if ((unsigned)(gx + 1) < WV) v.y = __ldg(p + 1);
                if ((unsigned)(gx + 2) < WV) v.z = __ldg(p + 2);
                if ((unsigned)(gx + 3) < WV) v.w = __ldg(p + 3);
            }
        }
        ((float4*)tile)[e4] = v;
    }

    const int lx = threadIdx.x & 31;      // warp lanes span x (coalesced I/O)
    const int ly = threadIdx.x >> 5;      // 0..31
    const int w = tx0 + lx;
    const int h = ty0 + ly;
    const float wf = (float)w, hf = (float)h;

    const float rf = __ldg(rf_ptr);
    const float CD = (float)DV / (float)(DV - 1);
    const float CH = (float)HV / (float)(HV - 1);
    const float CW = (float)WV / (float)(WV - 1);

    const int idx0 = (tz0 * HV + h) * WV + w;

    // Prefetch slice 0's flow2 so the DRAM latency overlaps staging + sync.
    float nf2z = __ldg(flow2 + idx0);
    float nf2y = __ldg(flow2 + VOL + idx0);
    float nf2x = __ldg(flow2 + 2 * VOL + idx0);

    __syncthreads();

#pragma unroll
    for (int i = 0; i < TZ; i++) {
        const int d = tz0 + i;
        const float df = (float)d;
        const int idx = idx0 + i * SLICE;

        float f2z = nf2z, f2y = nf2y, f2x = nf2x;
        if (i < TZ - 1) {                  // prefetch next slice's flow2
            nf2z = __ldg(flow2 + idx + SLICE);
            nf2y = __ldg(flow2 + VOL + idx + SLICE);
            nf2x = __ldg(flow2 + 2 * VOL + idx + SLICE);
        }

        // ---- Stage 1: flow1 warped by grid+flow2*rf (coords treated as
        // normalized by the reference -> almost always fully OOB -> zero).
        // Exact in-range conditions: |gx1|,|gz1| < 1.00625, |gy1| < 1.00521;
        // 1.0065 is a conservative superset, slow path re-checks per corner.
        float gz1 = df + f2z * rf;
        float gy1 = hf + f2y * rf;
        float gx1 = wf + f2x * rf;

        float fw[3] = {0.f, 0.f, 0.f};
        float m = fmaxf(fmaxf(fabsf(gx1), fabsf(gy1)), fabsf(gz1));
        if (m < 1.0065f)
            tri3_slow(flow1, gx1, gy1, gz1, fw);

        float of0 = fw[0] + f2z;
        float of1 = fw[1] + f2y;
        float of2 = fw[2] + f2x;

        // ---- Stage 2: resample src at grid + out_flow*rf (renormalized).
        float nl0 = df + of0 * rf;
        float nl1 = hf + of1 * rf;
        float nl2 = wf + of2 * rf;
        float iz2 = fmaf(nl0, CD, -0.5f);
        float iy2 = fmaf(nl1, CH, -0.5f);
        float ix2 = fmaf(nl2, CW, -0.5f);

        float x0f = floorf(ix2), y0f = floorf(iy2), z0f = floorf(iz2);
        float tx = ix2 - x0f, ty = iy2 - y0f, tz = iz2 - z0f;
        int x0 = (int)x0f, y0 = (int)y0f, z0 = (int)z0f;
        int sx = x0 - sxlo, sy = y0 - sylo, sz = z0 - szlo;

        float img;
        if ((unsigned)sx <= (EX - 2) &&
            (unsigned)sy <= (EY - 2) &&
            (unsigned)sz <= (EZ - 2)) {
            const float* p = tile + (sz * EY + sy) * EX + sx;
            const float* q = p + EXY;
            float v000 = p[0],  v001 = p[1];
            float v010 = p[EX], v011 = p[EX + 1];
            float v100 = q[0],  v101 = q[1];
            float v110 = q[EX], v111 = q[EX + 1];
            float c00 = fmaf(v001 - v000, tx, v000);
            float c01 = fmaf(v011 - v010, tx, v010);
            float c10 = fmaf(v101 - v100, tx, v100);
            float c11 = fmaf(v111 - v110, tx, v110);
            float c0  = fmaf(c01 - c00, ty, c00);
            float c1  = fmaf(c11 - c10, ty, c10);
            img = fmaf(c1 - c0, tz, c0);
        } else {
            img = tri1_global(src, x0, y0, z0, tx, ty, tz);
        }

        // ---- Outputs: deform_2_img [V], then out_flow [3V].
        out[idx]           = img;
        out[VOL + idx]     = of0;
        out[2 * VOL + idx] = of1;
        out[3 * VOL + idx] = of2;
    }
}

extern "C" void kernel_launch(void* const* d_in, const int* in_sizes, int n_in,
                              void* d_out, int out_size) {
    const float* src   = (const float*)d_in[0];
    const float* flow1 = (const float*)d_in[1];
    const float* flow2 = (const float*)d_in[2];
    // d_in[3] = meshgrid (recomputed in-kernel)
    const float* rf    = (const float*)d_in[4];
    float* out = (float*)d_out;

    // Deterministic, capture-safe: opt in to >48KB dynamic smem.
    cudaFuncSetAttribute(spatial_transformer_tiled,
                         cudaFuncAttributeMaxDynamicSharedMemorySize,
                         SMEM_BYTES);

    dim3 grid(WV / TX, HV / TY, DV / TZ);   // 5 x 6 x 20 = 600 blocks
    spatial_transformer_tiled<<<grid, NTHREADS, SMEM_BYTES>>>(src, flow1, flow2,
                                                              rf, out);
}

// round 16
// speedup vs baseline: 1.2078x; 1.0688x over previous
#include <cuda_runtime.h>

#define DV 160
#define HV 192
#define WV 160
#define VOL (DV * HV * WV)     // 4,915,200
#define SLICE (HV * WV)        // 30,720

// ---- Tile: 32x32x8 voxels, one 1024-thread block, 600 blocks ----
#define TX 32
#define TY 32
#define TZ 8
#define HXL 8                   // x halo low (mult of 4: float4-aligned rows)
#define HYL 8
#define HZL 7
#define EX 48                   // x: [tx0-8, tx0+40)   margins 8 / 7
#define EY 49                   // y: [ty0-8, ty0+41)   margins 8 / 8
#define EZ 22                   // z: [tz0-7, tz0+15)   margins 7 / 6
#define EXY (EX * EY)           // 2352
#define SMEM_ELEMS (EX * EY * EZ)    // 51744
#define SMEM_BYTES (SMEM_ELEMS * 4)  // 206,976 B -> 1 block/SM, 32 warps
#define NTHREADS 1024

// Zero-padding trilinear for the 3-channel flow1 volume. Rare path (stage-1
// coords are effectively un-normalized twice -> >99.99% of voxels fully OOB).
__device__ __noinline__ void tri3_slow(const float* __restrict__ vol,
                                       float gx1, float gy1, float gz1,
                                       float* __restrict__ o) {
    float ix = fmaf(gx1, 80.f, 79.5f);   // ((g+1)*160-1)/2
    float iy = fmaf(gy1, 96.f, 95.5f);   // ((g+1)*192-1)/2
    float iz = fmaf(gz1, 80.f, 79.5f);
    float x0f = floorf(ix), y0f = floorf(iy), z0f = floorf(iz);
    float tx = ix - x0f, ty = iy - y0f, tz = iz - z0f;
    int x0 = (int)x0f, y0 = (int)y0f, z0 = (int)z0f;
    float wx[2] = {1.f - tx, tx};
    float wy[2] = {1.f - ty, ty};
    float wz[2] = {1.f - tz, tz};
#pragma unroll
    for (int dz = 0; dz < 2; dz++) {
        int zc = z0 + dz;
        if (zc < 0 || zc >= DV) continue;
#pragma unroll
        for (int dy = 0; dy < 2; dy++) {
            int yc = y0 + dy;
            if (yc < 0 || yc >= HV) continue;
            int base = (zc * HV + yc) * WV;
            float wzy = wz[dz] * wy[dy];
#pragma unroll
            for (int dx = 0; dx < 2; dx++) {
                int xc = x0 + dx;
                if (xc < 0 || xc >= WV) continue;
                float wgt = wzy * wx[dx];
                int off = base + xc;
                o[0] = fmaf(__ldg(vol + off),           wgt, o[0]);
                o[1] = fmaf(__ldg(vol + VOL + off),     wgt, o[1]);
                o[2] = fmaf(__ldg(vol + 2 * VOL + off), wgt, o[2]);
            }
        }
    }
}

// Fallback: global-memory src sample (zeros padding) for voxels whose stencil
// escapes the smem halo (~0.1% of voxels with the wide halos).
__device__ __noinline__ float tri1_global(const float* __restrict__ vol,
                                          int x0, int y0, int z0,
                                          float tx, float ty, float tz) {
    if (x0 <= -2 || x0 >= WV || y0 <= -2 || y0 >= HV || z0 <= -2 || z0 >= DV)
        return 0.f;
    float wx[2] = {1.f - tx, tx};
    float wy[2] = {1.f - ty, ty};
    float wz[2] = {1.f - tz, tz};
    float acc = 0.f;
#pragma unroll
    for (int dz = 0; dz < 2; dz++) {
        int zc = z0 + dz;
        if (zc < 0 || zc >= DV) continue;
#pragma unroll
        for (int dy = 0; dy < 2; dy++) {
            int yc = y0 + dy;
            if (yc < 0 || yc >= HV) continue;
            int base = (zc * HV + yc) * WV;
            float wzy = wz[dz] * wy[dy];
#pragma unroll
            for (int dx = 0; dx < 2; dx++) {
                int xc = x0 + dx;
                if (xc < 0 || xc >= WV) continue;
                acc = fmaf(__ldg(vol + base + xc), wzy * wx[dx], acc);
            }
        }
    }
    return acc;
}

__global__ void __launch_bounds__(NTHREADS, 1)
spatial_transformer_tiled(const float* __restrict__ src,
                          const float* __restrict__ flow1,
                          const float* __restrict__ flow2,
                          const float* __restrict__ rf_ptr,
                          float* __restrict__ out) {
    extern __shared__ float tile[];

    const int tx0 = blockIdx.x * TX;
    const int ty0 = blockIdx.y * TY;
    const int tz0 = blockIdx.z * TZ;
    const int sxlo = tx0 - HXL;
    const int sylo = ty0 - HYL;
    const int szlo = tz0 - HZL;

    // ---- Stage src tile (+halo) into smem with float4 rows.
    // Volume-OOB cells -> 0 (zeros padding becomes free in the fast path).
#pragma unroll 2
    for (int e4 = threadIdx.x; e4 < SMEM_ELEMS / 4; e4 += NTHREADS) {
        int ex4 = e4 % (EX / 4);          // 0..11
        int row = e4 / (EX / 4);
        int ey  = row % EY;
        int ez  = row / EY;
        int gx = sxlo + ex4 * 4;
        int gy = sylo + ey;
        int gz = szlo + ez;
        float4 v = make_float4(0.f, 0.f, 0.f, 0.f);
        if ((unsigned)gy < HV && (unsigned)gz < DV) {
            const float* p = src + (gz * HV + gy) * WV + gx;
            if (gx >= 0 && gx + 3 < WV) {
                v = __ldg((const float4*)p);          // aligned: gx % 4 == 0
            } else {
                if ((unsigned)(gx + 0) < WV) v.x = __ldg(p + 0);
                if ((unsigned)(gx + 1) < WV) v.y = __ldg(p + 1);
                if ((unsigned)(gx + 2) < WV) v.z = __ldg(p + 2);
                if ((unsigned)(gx + 3) < WV) v.w = __ldg(p + 3);
            }
        }
        ((float4*)tile)[e4] = v;
    }

    const int lx = threadIdx.x & 31;      // warp lanes span x (coalesced I/O)
    const int ly = threadIdx.x >> 5;      // 0..31
    const int w = tx0 + lx;
    const int h = ty0 + ly;
    const float wf = (float)w, hf = (float)h;

    const float rf = __ldg(rf_ptr);
    const float CD = (float)DV / (float)(DV - 1);
    const float CH = (float)HV / (float)(HV - 1);
    const float CW = (float)WV / (float)(WV - 1);

    const int idx0 = (tz0 * HV + h) * WV + w;

    // Prefetch the first z-PAIR's flow2 (6 values) before the barrier so the
    // DRAM latency overlaps staging + sync.
    float nf2z0 = __ldg(flow2 + idx0);
    float nf2y0 = __ldg(flow2 + VOL + idx0);
    float nf2x0 = __ldg(flow2 + 2 * VOL + idx0);
    float nf2z1 = __ldg(flow2 + idx0 + SLICE);
    float nf2y1 = __ldg(flow2 + VOL + idx0 + SLICE);
    float nf2x1 = __ldg(flow2 + 2 * VOL + idx0 + SLICE);

    __syncthreads();

    // ---- Main loop: 2 z-slices per iteration (independent pipelines -> ILP).
#pragma unroll
    for (int ii = 0; ii < TZ; ii += 2) {
        const int idxA = idx0 + ii * SLICE;
        const int idxB = idxA + SLICE;
        const float dfA = (float)(tz0 + ii);
        const float dfB = dfA + 1.f;

        float f2z[2] = {nf2z0, nf2z1};
        float f2y[2] = {nf2y0, nf2y1};
        float f2x[2] = {nf2x0, nf2x1};
        if (ii < TZ - 2) {                 // prefetch next pair
            nf2z0 = __ldg(flow2 + idxB + SLICE);
            nf2y0 = __ldg(flow2 + VOL + idxB + SLICE);
            nf2x0 = __ldg(flow2 + 2 * VOL + idxB + SLICE);
            nf2z1 = __ldg(flow2 + idxB + 2 * SLICE);
            nf2y1 = __ldg(flow2 + VOL + idxB + 2 * SLICE);
            nf2x1 = __ldg(flow2 + 2 * VOL + idxB + 2 * SLICE);
        }

        float img[2], of0[2], of1[2], of2[2];

#pragma unroll
        for (int j = 0; j < 2; j++) {
            const float df = (j == 0) ? dfA : dfB;

            // ---- Stage 1: flow1 warped by grid+flow2*rf (coords treated as
            // normalized by the reference -> almost always fully OOB -> 0).
            float gz1 = df + f2z[j] * rf;
            float gy1 = hf + f2y[j] * rf;
            float gx1 = wf + f2x[j] * rf;

            float fw0 = 0.f, fw1 = 0.f, fw2 = 0.f;
            float m = fmaxf(fmaxf(fabsf(gx1), fabsf(gy1)), fabsf(gz1));
            if (m < 1.0065f) {             // conservative superset of in-range
                float fwv[3] = {0.f, 0.f, 0.f};
                tri3_slow(flow1, gx1, gy1, gz1, fwv);
                fw0 = fwv[0]; fw1 = fwv[1]; fw2 = fwv[2];
            }
            of0[j] = fw0 + f2z[j];
            of1[j] = fw1 + f2y[j];
            of2[j] = fw2 + f2x[j];

            // ---- Stage 2: nl = grid + out_flow*rf = g1 + fw*rf (reassoc).
            float nl0 = fmaf(fw0, rf, gz1);
            float nl1 = fmaf(fw1, rf, gy1);
            float nl2 = fmaf(fw2, rf, gx1);
            float iz2 = fmaf(nl0, CD, -0.5f);
            float iy2 = fmaf(nl1, CH, -0.5f);
            float ix2 = fmaf(nl2, CW, -0.5f);

            float x0f = floorf(ix2), y0f = floorf(iy2), z0f = floorf(iz2);
            float tx = ix2 - x0f, ty = iy2 - y0f, tz = iz2 - z0f;
            int x0 = (int)x0f, y0 = (int)y0f, z0 = (int)z0f;
            int sx = x0 - sxlo, sy = y0 - sylo, sz = z0 - szlo;

            if ((unsigned)sx <= (EX - 2) &&
                (unsigned)sy <= (EY - 2) &&
                (unsigned)sz <= (EZ - 2)) {
                const float* p = tile + (sz * EY + sy) * EX + sx;
                const float* q = p + EXY;
                float v000 = p[0],  v001 = p[1];
                float v010 = p[EX], v011 = p[EX + 1];
                float v100 = q[0],  v101 = q[1];
                float v110 = q[EX], v111 = q[EX + 1];
                float c00 = fmaf(v001 - v000, tx, v000);
                float c01 = fmaf(v011 - v010, tx, v010);
                float c10 = fmaf(v101 - v100, tx, v100);
                float c11 = fmaf(v111 - v110, tx, v110);
                float c0  = fmaf(c01 - c00, ty, c00);
                float c1  = fmaf(c11 - c10, ty, c10);
                img[j] = fmaf(c1 - c0, tz, c0);
            } else {
                img[j] = tri1_global(src, x0, y0, z0, tx, ty, tz);
            }
        }

        // ---- Outputs: deform_2_img [V], then out_flow [3V].
        out[idxA]           = img[0];
        out[VOL + idxA]     = of0[0];
        out[2 * VOL + idxA] = of1[0];
        out[3 * VOL + idxA] = of2[0];
        out[idxB]           = img[1];
        out[VOL + idxB]     = of0[1];
        out[2 * VOL + idxB] = of1[1];
        out[3 * VOL + idxB] = of2[1];
    }
}

extern "C" void kernel_launch(void* const* d_in, const int* in_sizes, int n_in,
                              void* d_out, int out_size) {
    const float* src   = (const float*)d_in[0];
    const float* flow1 = (const float*)d_in[1];
    const float* flow2 = (const float*)d_in[2];
    // d_in[3] = meshgrid (recomputed in-kernel)
    const float* rf    = (const float*)d_in[4];
    float* out = (float*)d_out;

    // Deterministic, capture-safe: opt in to >48KB dynamic smem.
    cudaFuncSetAttribute(spatial_transformer_tiled,
                         cudaFuncAttributeMaxDynamicSharedMemorySize,
                         SMEM_BYTES);

    dim3 grid(WV / TX, HV / TY, DV / TZ);   // 5 x 6 x 20 = 600 blocks
    spatial_transformer_tiled<<<grid, NTHREADS, SMEM_BYTES>>>(src, flow1, flow2,
                                                              rf, out);
}